// round 1
// baseline (speedup 1.0000x reference)
#include <cuda_runtime.h>

#define B_  4
#define T_  2048
#define C_  1024
#define NH_ 16
#define HS_ 64
#define M_  (B_*T_)   // 8192

// Scratch (allocation-free rule: static __device__ arrays)
__device__ float g_q[(size_t)M_ * C_];   // [B,H,T,HS]
__device__ float g_k[(size_t)M_ * C_];   // [B,H,T,HS]
__device__ float g_v[(size_t)M_ * C_];   // [B,H,T,HS]
__device__ float g_y[(size_t)M_ * C_];   // [B,T,C]

// ---------------------------------------------------------------------------
// SGEMM core: out = A[M,K=1024] * W[K=1024,N=1024]
// 128x128 block tile, BK=8, 256 threads, 8x8 per-thread micro tile.
// head_out=true writes to [B,H,T,HS] layout instead of [M,N].
// ---------------------------------------------------------------------------
__device__ __forceinline__ void gemm_core(const float* __restrict__ A,
                                          const float* __restrict__ W,
                                          float* __restrict__ out,
                                          bool head_out)
{
    __shared__ float As[8][128];   // transposed A tile: As[k][m]
    __shared__ float Bs[8][128];   // Bs[k][n]

    const int tid  = threadIdx.x;
    const int brow = blockIdx.y * 128;
    const int bcol = blockIdx.x * 128;
    const int tx   = tid & 15;     // 16 thread cols
    const int ty   = tid >> 4;     // 16 thread rows

    // A tile loader: 128 rows x 8 cols; 256 threads x float4
    const int a_row = tid >> 1;
    const int a_col = (tid & 1) * 4;
    // B tile loader: 8 rows x 128 cols; 256 threads x float4
    const int b_row = tid >> 5;
    const int b_col = (tid & 31) * 4;

    const float* Ap = A + (size_t)(brow + a_row) * C_ + a_col;
    const float* Bp = W + (size_t)b_row * C_ + bcol + b_col;

    float acc[8][8];
    #pragma unroll
    for (int i = 0; i < 8; i++)
        #pragma unroll
        for (int j = 0; j < 8; j++) acc[i][j] = 0.f;

    for (int k0 = 0; k0 < C_; k0 += 8) {
        float4 av = *(const float4*)Ap;  Ap += 8;
        float4 bv = *(const float4*)Bp;  Bp += 8 * C_;
        __syncthreads();
        As[a_col + 0][a_row] = av.x;
        As[a_col + 1][a_row] = av.y;
        As[a_col + 2][a_row] = av.z;
        As[a_col + 3][a_row] = av.w;
        *(float4*)&Bs[b_row][b_col] = bv;
        __syncthreads();

        #pragma unroll
        for (int kk = 0; kk < 8; kk++) {
            float4 a0 = *(const float4*)&As[kk][ty * 8];
            float4 a1 = *(const float4*)&As[kk][ty * 8 + 4];
            float4 b0 = *(const float4*)&Bs[kk][tx * 8];
            float4 b1 = *(const float4*)&Bs[kk][tx * 8 + 4];
            float ar[8] = {a0.x, a0.y, a0.z, a0.w, a1.x, a1.y, a1.z, a1.w};
            float br[8] = {b0.x, b0.y, b0.z, b0.w, b1.x, b1.y, b1.z, b1.w};
            #pragma unroll
            for (int i = 0; i < 8; i++)
                #pragma unroll
                for (int j = 0; j < 8; j++)
                    acc[i][j] += ar[i] * br[j];
        }
    }

    if (head_out) {
        // n-range [bcol+tx*8, +8) always lies within one 64-wide head block,
        // so the 8 outputs are contiguous in d -> float4 stores.
        const int n0 = bcol + tx * 8;
        const int h  = n0 >> 6;
        const int d0 = n0 & 63;
        #pragma unroll
        for (int i = 0; i < 8; i++) {
            int m = brow + ty * 8 + i;
            int b = m >> 11;          // /T_
            int t = m & (T_ - 1);
            float* dst = out + (((size_t)b * NH_ + h) * T_ + t) * HS_ + d0;
            #pragma unroll
            for (int j = 0; j < 8; j += 4) {
                float4 v = make_float4(acc[i][j], acc[i][j+1], acc[i][j+2], acc[i][j+3]);
                *(float4*)(dst + j) = v;
            }
        }
    } else {
        #pragma unroll
        for (int i = 0; i < 8; i++) {
            int m = brow + ty * 8 + i;
            #pragma unroll
            for (int j = 0; j < 8; j += 4) {
                float4 v = make_float4(acc[i][j], acc[i][j+1], acc[i][j+2], acc[i][j+3]);
                *(float4*)&out[(size_t)m * C_ + bcol + tx * 8 + j] = v;
            }
        }
    }
}

__global__ __launch_bounds__(256)
void sgemm_qkv(const float* __restrict__ x, const float* __restrict__ Wq,
               const float* __restrict__ Wk, const float* __restrict__ Wv)
{
    const float* W = (blockIdx.z == 0) ? Wq : (blockIdx.z == 1) ? Wk : Wv;
    float*       o = (blockIdx.z == 0) ? g_q : (blockIdx.z == 1) ? g_k : g_v;
    gemm_core(x, W, o, true);
}

__global__ __launch_bounds__(256)
void sgemm_proj(const float* __restrict__ Wp, float* __restrict__ out)
{
    gemm_core(g_y, Wp, out, false);
}

// ---------------------------------------------------------------------------
// Flash attention (causal, fp32). Grid: (T/64, B*NH). 64 threads/CTA.
// Thread t owns q-row (qt*64 + t): q[64] and acc[64] live in registers.
// K/V tiles (64x64) staged in smem; all lanes read the same element ->
// broadcast (conflict-free). Online softmax with 16-wide chunks.
// ---------------------------------------------------------------------------
__global__ __launch_bounds__(64)
void attn_kernel()
{
    __shared__ float Ks[64 * 64];
    __shared__ float Vs[64 * 64];

    const int qt   = blockIdx.x;
    const int bh   = blockIdx.y;
    const int tid  = threadIdx.x;
    const int qidx = qt * 64 + tid;

    const float* Qb = g_q + ((size_t)bh * T_ + qidx) * HS_;
    const float* Kb = g_k + (size_t)bh * T_ * HS_;
    const float* Vb = g_v + (size_t)bh * T_ * HS_;

    float q[64];
    #pragma unroll
    for (int d = 0; d < 64; d++) q[d] = Qb[d] * 0.125f;   // 1/sqrt(HS)

    float acc[64];
    #pragma unroll
    for (int d = 0; d < 64; d++) acc[d] = 0.f;
    float mrow = -1e30f, lrow = 0.f;

    for (int kt = 0; kt <= qt; kt++) {
        __syncthreads();
        const float4* Kt = (const float4*)(Kb + (size_t)kt * 64 * HS_);
        const float4* Vt = (const float4*)(Vb + (size_t)kt * 64 * HS_);
        #pragma unroll
        for (int i = 0; i < 16; i++) {
            ((float4*)Ks)[tid + i * 64] = Kt[tid + i * 64];
            ((float4*)Vs)[tid + i * 64] = Vt[tid + i * 64];
        }
        __syncthreads();

        const bool diag = (kt == qt);
        for (int jc = 0; jc < 64; jc += 16) {
            if (diag && (qt * 64 + jc) > qidx) break;  // fully-masked chunk

            float s[16];
            float cmax = -1e30f;
            #pragma unroll
            for (int j = 0; j < 16; j++) {
                const float* kr = Ks + (jc + j) * 64;
                float s0 = 0.f, s1 = 0.f, s2 = 0.f, s3 = 0.f;
                #pragma unroll
                for (int d = 0; d < 64; d += 4) {
                    float4 kv = *(const float4*)(kr + d);
                    s0 += q[d]     * kv.x;
                    s1 += q[d + 1] * kv.y;
                    s2 += q[d + 2] * kv.z;
                    s3 += q[d + 3] * kv.w;
                }
                float sum = (s0 + s1) + (s2 + s3);
                if (diag && (kt * 64 + jc + j) > qidx) sum = -1e30f;
                s[j] = sum;
                cmax = fmaxf(cmax, sum);
            }

            float mnew = fmaxf(mrow, cmax);
            float f = __expf(mrow - mnew);
            mrow = mnew;
            lrow *= f;
            #pragma unroll
            for (int d = 0; d < 64; d++) acc[d] *= f;

            #pragma unroll
            for (int j = 0; j < 16; j++) {
                float p = __expf(s[j] - mnew);
                lrow += p;
                const float* vr = Vs + (jc + j) * 64;
                #pragma unroll
                for (int d = 0; d < 64; d += 4) {
                    float4 vv = *(const float4*)(vr + d);
                    acc[d]     += p * vv.x;
                    acc[d + 1] += p * vv.y;
                    acc[d + 2] += p * vv.z;
                    acc[d + 3] += p * vv.w;
                }
            }
        }
    }

    const float inv = 1.0f / lrow;
    const int b = bh >> 4;          // / NH_
    const int h = bh & (NH_ - 1);
    float* yp = g_y + (size_t)(b * T_ + qidx) * C_ + h * HS_;
    #pragma unroll
    for (int d = 0; d < 64; d += 4) {
        float4 o = make_float4(acc[d] * inv, acc[d+1] * inv, acc[d+2] * inv, acc[d+3] * inv);
        *(float4*)(yp + d) = o;
    }
}

// ---------------------------------------------------------------------------
extern "C" void kernel_launch(void* const* d_in, const int* in_sizes, int n_in,
                              void* d_out, int out_size)
{
    (void)in_sizes; (void)n_in; (void)out_size;
    const float* x  = (const float*)d_in[0];
    const float* Wk = (const float*)d_in[1];
    const float* Wq = (const float*)d_in[2];
    const float* Wv = (const float*)d_in[3];
    const float* Wp = (const float*)d_in[4];
    float* out = (float*)d_out;

    dim3 gq(C_ / 128, M_ / 128, 3);
    sgemm_qkv<<<gq, 256>>>(x, Wq, Wk, Wv);

    dim3 ga(T_ / 64, B_ * NH_);
    attn_kernel<<<ga, 64>>>();

    dim3 gp(C_ / 128, M_ / 128, 1);
    sgemm_proj<<<gp, 256>>>(Wp, out);
}

// round 4
// speedup vs baseline: 3.5898x; 3.5898x over previous
#include <cuda_runtime.h>
#include <cstdint>

#define B_  4
#define T_  2048
#define C_  1024
#define NH_ 16
#define HS_ 64
#define M_  (B_*T_)   // 8192

// ---------------- scratch (static device arrays: allocation-free) ----------
__device__ float g_q [(size_t)M_ * C_];   // [B,H,T,HS] tf32-rounded
__device__ float g_k [(size_t)M_ * C_];
__device__ float g_v [(size_t)M_ * C_];
__device__ float g_y [(size_t)M_ * C_];   // [B,T,C]   tf32-rounded
__device__ float g_xt[(size_t)M_ * C_];   // x rounded to tf32
__device__ float g_wt[(size_t)4 * C_ * C_]; // W^T (K-major, tf32): q,k,v,p

// ---------------- helpers ---------------------------------------------------
__device__ __forceinline__ float rn_tf32(float x) {
    uint32_t u;
    asm("cvt.rna.tf32.f32 %0, %1;" : "=r"(u) : "f"(x));
    return __uint_as_float(u);
}
__device__ __forceinline__ uint32_t fbits(float f) { return __float_as_uint(f); }
__device__ __forceinline__ float ex2(float x) {
    float y; asm("ex2.approx.f32 %0, %1;" : "=f"(y) : "f"(x)); return y;
}
__device__ __forceinline__ void mma_tf32(float* d, const uint32_t* a, const uint32_t* b) {
    asm volatile("mma.sync.aligned.m16n8k8.row.col.f32.tf32.tf32.f32 "
                 "{%0,%1,%2,%3}, {%4,%5,%6,%7}, {%8,%9}, {%0,%1,%2,%3};"
                 : "+f"(d[0]), "+f"(d[1]), "+f"(d[2]), "+f"(d[3])
                 : "r"(a[0]), "r"(a[1]), "r"(a[2]), "r"(a[3]), "r"(b[0]), "r"(b[1]));
}

// ---------------- prepass: round x to tf32 ---------------------------------
__global__ __launch_bounds__(256) void round_x_kernel(const float* __restrict__ x) {
    size_t i0 = ((size_t)blockIdx.x * 256 + threadIdx.x) * 4;
    const size_t stride = (size_t)gridDim.x * 256 * 4;
    for (int r = 0; r < 4; r++) {
        float4 v = *(const float4*)(x + i0);
        v.x = rn_tf32(v.x); v.y = rn_tf32(v.y); v.z = rn_tf32(v.z); v.w = rn_tf32(v.w);
        *(float4*)(g_xt + i0) = v;
        i0 += stride;
    }
}

// ---------------- prepass: transpose + round W -> g_wt[slot][n][k] ---------
__global__ __launch_bounds__(256) void transpose_w_kernel(const float* __restrict__ Wq,
                                                          const float* __restrict__ Wk,
                                                          const float* __restrict__ Wv,
                                                          const float* __restrict__ Wp) {
    __shared__ float tile[32][33];
    const int z = blockIdx.z;
    const float* src = (z == 0) ? Wq : (z == 1) ? Wk : (z == 2) ? Wv : Wp;
    float* dst = g_wt + ((size_t)z << 20);
    int x = blockIdx.x * 32 + threadIdx.x;   // n
    int y = blockIdx.y * 32 + threadIdx.y;   // k
    #pragma unroll
    for (int i = 0; i < 32; i += 8)
        tile[threadIdx.y + i][threadIdx.x] = src[(size_t)(y + i) * C_ + x];
    __syncthreads();
    int xo = blockIdx.y * 32 + threadIdx.x;  // k
    int yo = blockIdx.x * 32 + threadIdx.y;  // n
    #pragma unroll
    for (int i = 0; i < 32; i += 8)
        dst[(size_t)(yo + i) * C_ + xo] = rn_tf32(tile[threadIdx.x][threadIdx.y + i]);
}

// ---------------- tf32 mma.sync GEMM ----------------------------------------
// out[m,n] = sum_k A[m,k] * Bt[n,k]; 128x128x16 tiles, 256 thr, 64x32 warp tile
#define GBM 128
#define GBN 128
#define GBK 16
#define GPAD 20
#define NCH  (C_ / GBK)   // 64

__device__ __forceinline__ void gemm_core(const float* __restrict__ A,
                                          const float* __restrict__ Bt,
                                          float* __restrict__ outp, int head_out)
{
    __shared__ float As[2][GBM * GPAD];
    __shared__ float Bs[2][GBN * GPAD];

    const int tid = threadIdx.x, lane = tid & 31, wid = tid >> 5;
    const int wm = (wid >> 2) * 64;   // warp m offset (2 warps)
    const int wn = (wid & 3) * 32;    // warp n offset (4 warps)
    const int gi = lane >> 2, tg = lane & 3;

    const int brow = blockIdx.y * GBM, bcol = blockIdx.x * GBN;
    const int lr = tid >> 2;          // loader row 0..63
    const int lc = (tid & 3) * 4;     // loader col

    const float* Ag = A  + (size_t)(brow + lr) * C_ + lc;
    const float* Bg = Bt + (size_t)(bcol + lr) * C_ + lc;

    float acc[4][4][4];
    #pragma unroll
    for (int i = 0; i < 4; i++)
        #pragma unroll
        for (int j = 0; j < 4; j++)
            #pragma unroll
            for (int q = 0; q < 4; q++) acc[i][j][q] = 0.f;

    float4 pa0 = *(const float4*)Ag;
    float4 pa1 = *(const float4*)(Ag + (size_t)64 * C_);
    float4 pb0 = *(const float4*)Bg;
    float4 pb1 = *(const float4*)(Bg + (size_t)64 * C_);

    for (int c = 0; c < NCH; c++) {
        const int cur = c & 1;
        *(float4*)&As[cur][lr * GPAD + lc]        = pa0;
        *(float4*)&As[cur][(lr + 64) * GPAD + lc] = pa1;
        *(float4*)&Bs[cur][lr * GPAD + lc]        = pb0;
        *(float4*)&Bs[cur][(lr + 64) * GPAD + lc] = pb1;
        __syncthreads();
        if (c + 1 < NCH) {
            Ag += GBK; Bg += GBK;
            pa0 = *(const float4*)Ag;
            pa1 = *(const float4*)(Ag + (size_t)64 * C_);
            pb0 = *(const float4*)Bg;
            pb1 = *(const float4*)(Bg + (size_t)64 * C_);
        }
        #pragma unroll
        for (int ks = 0; ks < 2; ks++) {
            const int kb = ks * 8;
            uint32_t af[4][4], bf[4][2];
            #pragma unroll
            for (int ms = 0; ms < 4; ms++) {
                int r = wm + ms * 16 + gi;
                af[ms][0] = fbits(As[cur][r * GPAD + kb + tg]);
                af[ms][1] = fbits(As[cur][(r + 8) * GPAD + kb + tg]);
                af[ms][2] = fbits(As[cur][r * GPAD + kb + tg + 4]);
                af[ms][3] = fbits(As[cur][(r + 8) * GPAD + kb + tg + 4]);
            }
            #pragma unroll
            for (int ns = 0; ns < 4; ns++) {
                int n = wn + ns * 8 + gi;
                bf[ns][0] = fbits(Bs[cur][n * GPAD + kb + tg]);
                bf[ns][1] = fbits(Bs[cur][n * GPAD + kb + tg + 4]);
            }
            #pragma unroll
            for (int ms = 0; ms < 4; ms++)
                #pragma unroll
                for (int ns = 0; ns < 4; ns++)
                    mma_tf32(acc[ms][ns], af[ms], bf[ns]);
        }
    }

    #pragma unroll
    for (int ms = 0; ms < 4; ms++) {
        int r0 = brow + wm + ms * 16 + gi;
        int r1 = r0 + 8;
        #pragma unroll
        for (int ns = 0; ns < 4; ns++) {
            int n = bcol + wn + ns * 8 + tg * 2;
            if (head_out) {
                int h = n >> 6, d0 = n & 63;
                float* p0 = outp + (((size_t)(r0 >> 11) * NH_ + h) * T_ + (r0 & (T_-1))) * HS_ + d0;
                float* p1 = outp + (((size_t)(r1 >> 11) * NH_ + h) * T_ + (r1 & (T_-1))) * HS_ + d0;
                *(float2*)p0 = make_float2(rn_tf32(acc[ms][ns][0]), rn_tf32(acc[ms][ns][1]));
                *(float2*)p1 = make_float2(rn_tf32(acc[ms][ns][2]), rn_tf32(acc[ms][ns][3]));
            } else {
                *(float2*)(outp + (size_t)r0 * C_ + n) = make_float2(acc[ms][ns][0], acc[ms][ns][1]);
                *(float2*)(outp + (size_t)r1 * C_ + n) = make_float2(acc[ms][ns][2], acc[ms][ns][3]);
            }
        }
    }
}

__global__ __launch_bounds__(256, 2) void gemm_qkv_tc() {
    const int z = blockIdx.z;
    const float* Bt = g_wt + ((size_t)z << 20);
    float* o = (z == 0) ? g_q : (z == 1) ? g_k : g_v;
    gemm_core(g_xt, Bt, o, 1);
}
__global__ __launch_bounds__(256, 2) void gemm_proj_tc(float* __restrict__ out) {
    gemm_core(g_y, g_wt + ((size_t)3 << 20), out, 0);
}

// ---------------- flash attention with tf32 mma.sync ------------------------
// CTA = 128 thr (4 warps), one 64-row q tile of one head. Warp w owns rows
// w*16..w*16+15. Smem pads chosen conflict-free for fragment gather patterns.
#define PQ 68
#define PK 68
#define PVp 72
#define PP 68
#define ASMEM ((64*PQ + 64*PK + 64*PVp + 64*PP) * 4)   // 70656 B
#define L2E 1.4426950408889634f

__global__ __launch_bounds__(128) void attn_mma()
{
    extern __shared__ float sm[];
    float* Qs = sm;
    float* Ks = Qs + 64 * PQ;
    float* Vs = Ks + 64 * PK;
    float* Ps = Vs + 64 * PVp;

    const int qt = blockIdx.x, bh = blockIdx.y;
    const int tid = threadIdx.x, wid = tid >> 5, lane = tid & 31;
    const int gi = lane >> 2, tg = lane & 3;
    const int wm = wid * 16;

    const float* Qg = g_q + ((size_t)bh * T_ + (size_t)qt * 64) * HS_;
    const float* Kg = g_k + (size_t)bh * T_ * HS_;
    const float* Vg = g_v + (size_t)bh * T_ * HS_;

    // load Q tile (scale by 1/sqrt(HS) = 0.125, exact in tf32)
    #pragma unroll
    for (int i = 0; i < 8; i++) {
        int r = (tid >> 4) + i * 8, c4 = (tid & 15) * 4;
        float4 v = *(const float4*)(Qg + r * 64 + c4);
        v.x *= 0.125f; v.y *= 0.125f; v.z *= 0.125f; v.w *= 0.125f;
        *(float4*)&Qs[r * PQ + c4] = v;
    }

    float accO[8][4];
    #pragma unroll
    for (int ns = 0; ns < 8; ns++)
        #pragma unroll
        for (int q = 0; q < 4; q++) accO[ns][q] = 0.f;
    float m0 = -1e30f, m1 = -1e30f, l0 = 0.f, l1 = 0.f;

    const int q0 = qt * 64 + wm + gi, q1 = q0 + 8;

    for (int kt = 0; kt <= qt; kt++) {
        __syncthreads();
        #pragma unroll
        for (int i = 0; i < 8; i++) {
            int r = (tid >> 4) + i * 8, c4 = (tid & 15) * 4;
            *(float4*)&Ks[r * PK + c4]  = *(const float4*)(Kg + ((size_t)kt * 64 + r) * 64 + c4);
            *(float4*)&Vs[r * PVp + c4] = *(const float4*)(Vg + ((size_t)kt * 64 + r) * 64 + c4);
        }
        __syncthreads();

        // S = Q K^T  (warp's 16 x 64 scores)
        float sacc[8][4];
        #pragma unroll
        for (int ns = 0; ns < 8; ns++)
            #pragma unroll
            for (int q = 0; q < 4; q++) sacc[ns][q] = 0.f;
        #pragma unroll
        for (int ks = 0; ks < 8; ks++) {
            int kb = ks * 8;
            uint32_t a[4];
            a[0] = fbits(Qs[(wm + gi) * PQ + kb + tg]);
            a[1] = fbits(Qs[(wm + gi + 8) * PQ + kb + tg]);
            a[2] = fbits(Qs[(wm + gi) * PQ + kb + tg + 4]);
            a[3] = fbits(Qs[(wm + gi + 8) * PQ + kb + tg + 4]);
            #pragma unroll
            for (int ns = 0; ns < 8; ns++) {
                uint32_t b[2];
                b[0] = fbits(Ks[(ns * 8 + gi) * PK + kb + tg]);
                b[1] = fbits(Ks[(ns * 8 + gi) * PK + kb + tg + 4]);
                mma_tf32(sacc[ns], a, b);
            }
        }

        if (kt == qt) {   // causal mask on diagonal tile
            #pragma unroll
            for (int ns = 0; ns < 8; ns++) {
                int c0 = kt * 64 + ns * 8 + tg * 2;
                if (c0     > q0) sacc[ns][0] = -1e30f;
                if (c0 + 1 > q0) sacc[ns][1] = -1e30f;
                if (c0     > q1) sacc[ns][2] = -1e30f;
                if (c0 + 1 > q1) sacc[ns][3] = -1e30f;
            }
        }

        // online softmax
        float tm0 = -1e30f, tm1 = -1e30f;
        #pragma unroll
        for (int ns = 0; ns < 8; ns++) {
            tm0 = fmaxf(tm0, fmaxf(sacc[ns][0], sacc[ns][1]));
            tm1 = fmaxf(tm1, fmaxf(sacc[ns][2], sacc[ns][3]));
        }
        tm0 = fmaxf(tm0, __shfl_xor_sync(0xffffffffu, tm0, 1));
        tm0 = fmaxf(tm0, __shfl_xor_sync(0xffffffffu, tm0, 2));
        tm1 = fmaxf(tm1, __shfl_xor_sync(0xffffffffu, tm1, 1));
        tm1 = fmaxf(tm1, __shfl_xor_sync(0xffffffffu, tm1, 2));
        float nm0 = fmaxf(m0, tm0), nm1 = fmaxf(m1, tm1);
        float f0 = ex2((m0 - nm0) * L2E), f1 = ex2((m1 - nm1) * L2E);
        m0 = nm0; m1 = nm1;

        float ps0 = 0.f, ps1 = 0.f;
        #pragma unroll
        for (int ns = 0; ns < 8; ns++) {
            float p0 = ex2((sacc[ns][0] - nm0) * L2E);
            float p1 = ex2((sacc[ns][1] - nm0) * L2E);
            float p2 = ex2((sacc[ns][2] - nm1) * L2E);
            float p3 = ex2((sacc[ns][3] - nm1) * L2E);
            ps0 += p0 + p1; ps1 += p2 + p3;
            int c0 = ns * 8 + tg * 2;
            Ps[(wm + gi) * PP + c0]       = rn_tf32(p0);
            Ps[(wm + gi) * PP + c0 + 1]   = rn_tf32(p1);
            Ps[(wm + gi + 8) * PP + c0]     = rn_tf32(p2);
            Ps[(wm + gi + 8) * PP + c0 + 1] = rn_tf32(p3);
        }
        ps0 += __shfl_xor_sync(0xffffffffu, ps0, 1);
        ps0 += __shfl_xor_sync(0xffffffffu, ps0, 2);
        ps1 += __shfl_xor_sync(0xffffffffu, ps1, 1);
        ps1 += __shfl_xor_sync(0xffffffffu, ps1, 2);
        l0 = l0 * f0 + ps0;
        l1 = l1 * f1 + ps1;
        #pragma unroll
        for (int ns = 0; ns < 8; ns++) {
            accO[ns][0] *= f0; accO[ns][1] *= f0;
            accO[ns][2] *= f1; accO[ns][3] *= f1;
        }
        __syncwarp();   // Ps visible within warp (warp-private region)

        // O += P V
        #pragma unroll
        for (int ks = 0; ks < 8; ks++) {
            int kb = ks * 8;
            uint32_t a[4];
            a[0] = fbits(Ps[(wm + gi) * PP + kb + tg]);
            a[1] = fbits(Ps[(wm + gi + 8) * PP + kb + tg]);
            a[2] = fbits(Ps[(wm + gi) * PP + kb + tg + 4]);
            a[3] = fbits(Ps[(wm + gi + 8) * PP + kb + tg + 4]);
            #pragma unroll
            for (int ns = 0; ns < 8; ns++) {
                uint32_t b[2];
                b[0] = fbits(Vs[(kb + tg) * PVp + ns * 8 + gi]);
                b[1] = fbits(Vs[(kb + tg + 4) * PVp + ns * 8 + gi]);
                mma_tf32(accO[ns], a, b);
            }
        }
        __syncwarp();   // PV reads done before next tile's Ps writes
    }

    const float i0 = 1.f / l0, i1 = 1.f / l1;
    const int b = bh >> 4, h = bh & (NH_ - 1);
    float* y0 = g_y + ((size_t)b * T_ + q0) * C_ + h * HS_;
    float* y1 = g_y + ((size_t)b * T_ + q1) * C_ + h * HS_;
    #pragma unroll
    for (int ns = 0; ns < 8; ns++) {
        int c0 = ns * 8 + tg * 2;
        *(float2*)(y0 + c0) = make_float2(rn_tf32(accO[ns][0] * i0), rn_tf32(accO[ns][1] * i0));
        *(float2*)(y1 + c0) = make_float2(rn_tf32(accO[ns][2] * i1), rn_tf32(accO[ns][3] * i1));
    }
}

// ---------------------------------------------------------------------------
extern "C" void kernel_launch(void* const* d_in, const int* in_sizes, int n_in,
                              void* d_out, int out_size)
{
    (void)in_sizes; (void)n_in; (void)out_size;
    const float* x  = (const float*)d_in[0];
    const float* Wk = (const float*)d_in[1];
    const float* Wq = (const float*)d_in[2];
    const float* Wv = (const float*)d_in[3];
    const float* Wp = (const float*)d_in[4];
    float* out = (float*)d_out;

    static int attr_done = 0;
    if (!attr_done) {
        cudaFuncSetAttribute(attn_mma, cudaFuncAttributeMaxDynamicSharedMemorySize, ASMEM);
        attr_done = 1;
    }

    round_x_kernel<<<2048, 256>>>(x);
    transpose_w_kernel<<<dim3(32, 32, 4), dim3(32, 8)>>>(Wq, Wk, Wv, Wp);

    gemm_qkv_tc<<<dim3(C_ / GBN, M_ / GBM, 3), 256>>>();

    attn_mma<<<dim3(T_ / 64, B_ * NH_), 128, ASMEM>>>();

    gemm_proj_tc<<<dim3(C_ / GBN, M_ / GBM, 1), 256>>>(out);
}